// round 16
// baseline (speedup 1.0000x reference)
#include <cuda_runtime.h>
#include <cuda_fp16.h>
#include <cstdint>

// Problem constants
#define Bn   2
#define Sn   2048
#define EMB  2048
#define NH   16
#define NKV  4
#define DH   128
#define MROWS (Bn*Sn)   // 4096

// fp16 scratch (device globals; no runtime allocation allowed)
__device__ __half g_hq [(size_t)MROWS*EMB];
__device__ __half g_hk [(size_t)MROWS*EMB];
__device__ __half g_hv [(size_t)MROWS*EMB];
__device__ __half g_hWq[(size_t)EMB*EMB];        // scale*log2e folded
__device__ __half g_hWk[(size_t)EMB*NKV*DH];     // scale folded
__device__ __half g_hWv[(size_t)EMB*NKV*DH];
__device__ __half g_hWo[(size_t)EMB*EMB];
__device__ __half g_qh [(size_t)Bn*NH*Sn*DH];    // [B,H,S,D]
__device__ __half g_kh [(size_t)Bn*NKV*Sn*DH];
__device__ __half g_vh [(size_t)Bn*NKV*Sn*DH];
__device__ __half g_z  [(size_t)Bn*Sn*NH*DH];    // [B,S,H*D]

__device__ __forceinline__ void mma_f16(float c[4], const uint32_t a[4], uint32_t b0, uint32_t b1) {
    asm volatile("mma.sync.aligned.m16n8k16.row.col.f32.f16.f16.f32 "
        "{%0,%1,%2,%3},{%4,%5,%6,%7},{%8,%9},{%0,%1,%2,%3};"
        : "+f"(c[0]), "+f"(c[1]), "+f"(c[2]), "+f"(c[3])
        : "r"(a[0]), "r"(a[1]), "r"(a[2]), "r"(a[3]), "r"(b0), "r"(b1));
}
__device__ __forceinline__ void ldmx4(uint32_t& r0, uint32_t& r1, uint32_t& r2, uint32_t& r3, uint32_t addr) {
    asm volatile("ldmatrix.sync.aligned.m8n8.x4.shared.b16 {%0,%1,%2,%3}, [%4];"
        : "=r"(r0), "=r"(r1), "=r"(r2), "=r"(r3) : "r"(addr));
}
__device__ __forceinline__ void ldmx4t(uint32_t& r0, uint32_t& r1, uint32_t& r2, uint32_t& r3, uint32_t addr) {
    asm volatile("ldmatrix.sync.aligned.m8n8.x4.trans.shared.b16 {%0,%1,%2,%3}, [%4];"
        : "=r"(r0), "=r"(r1), "=r"(r2), "=r"(r3) : "r"(addr));
}
__device__ __forceinline__ uint32_t packh2(float lo, float hi) {
    uint32_t r;
    asm("cvt.rn.f16x2.f32 %0, %1, %2;" : "=r"(r) : "f"(hi), "f"(lo));
    return r;
}
__device__ __forceinline__ float ex2f(float x) {
    float r; asm("ex2.approx.ftz.f32 %0, %1;" : "=f"(r) : "f"(x)); return r;
}
__device__ __forceinline__ void cp_async16(uint32_t saddr, const void* gptr) {
    asm volatile("cp.async.ca.shared.global [%0], [%1], 16;\n"
        :: "r"(saddr), "l"(__cvta_generic_to_global(gptr)));
}
__device__ __forceinline__ void cp_async_commit() { asm volatile("cp.async.commit_group;\n"); }
__device__ __forceinline__ void cp_async_wait0()  { asm volatile("cp.async.wait_group 0;\n"); }
__device__ __forceinline__ void cp_async_wait2()  { asm volatile("cp.async.wait_group 2;\n"); }

// ---------------------------------------------------------------------------
// Fused fp32 -> fp16 convert for all 7 tensors, one launch (simple 1:1 map).
// ---------------------------------------------------------------------------
#define NQ4  ((long)MROWS*EMB/4)
#define WQ4  ((long)EMB*EMB/4)
#define WK4  ((long)EMB*NKV*DH/4)
#define CVT_TOTAL (3*NQ4 + 2*WQ4 + 2*WK4)

__global__ __launch_bounds__(256)
void cvt_all(const float4* __restrict__ q, const float4* __restrict__ k, const float4* __restrict__ v,
             const float4* __restrict__ Wq, const float4* __restrict__ Wk,
             const float4* __restrict__ Wv, const float4* __restrict__ Wo,
             uint2* hq, uint2* hk, uint2* hv, uint2* hWq, uint2* hWk, uint2* hWv, uint2* hWo,
             float scaleQ, float scaleK)
{
    long i = (long)blockIdx.x * blockDim.x + threadIdx.x;
    if (i >= CVT_TOTAL) return;
    const float4* src; uint2* dst; long off; float s = 1.0f;
    if      (i <     NQ4)             { src = q;  dst = hq;  off = i; }
    else if (i < 2 * NQ4)             { src = k;  dst = hk;  off = i - NQ4; }
    else if (i < 3 * NQ4)             { src = v;  dst = hv;  off = i - 2 * NQ4; }
    else if (i < 3 * NQ4 + WQ4)       { src = Wq; dst = hWq; off = i - 3 * NQ4; s = scaleQ; }
    else if (i < 3 * NQ4 + WQ4 + WK4) { src = Wk; dst = hWk; off = i - 3 * NQ4 - WQ4; s = scaleK; }
    else if (i < 3 * NQ4 + WQ4 + 2 * WK4) { src = Wv; dst = hWv; off = i - 3 * NQ4 - WQ4 - WK4; }
    else                              { src = Wo; dst = hWo; off = i - 3 * NQ4 - WQ4 - 2 * WK4; }
    float4 x = src[off];
    __half2 h0 = __floats2half2_rn(x.x * s, x.y * s);
    __half2 h1 = __floats2half2_rn(x.z * s, x.w * s);
    uint2 u; u.x = *reinterpret_cast<uint32_t*>(&h0); u.y = *reinterpret_cast<uint32_t*>(&h1);
    dst[off] = u;
}

// ---------------------------------------------------------------------------
// GEMM core: 128 threads (4 warps, 2x2), warp tile 64x64.
// BM=BN=128, BK=32, 4-stage cp.async; empty-commit tail keeps wait_group 2 sound.
// ---------------------------------------------------------------------------
struct GemmCore {
    static constexpr int BM = 128, BN = 128, BK = 32, STAGES = 4, NT = 128;
    static constexpr int LDA = 40, LDB = 136;
    static constexpr int ASZ = BM * LDA, BSZ = BK * LDB;
};

__device__ __forceinline__ void gemm_mainloop(
    const __half* __restrict__ A, const __half* __restrict__ W,
    int N, int K, int m0, int n0,
    int tid, int wid, int lane, float acc[4][8][4], __half* smh)
{
    using GC = GemmCore;
    const uint32_t sA = (uint32_t)__cvta_generic_to_shared(smh);
    const uint32_t sB = sA + (uint32_t)(GC::STAGES * GC::ASZ) * 2u;
    const int wm = (wid >> 1) * 64;
    const int wn = (wid & 1) * 64;
    const int lrow = lane & 15;
    const int lcol = (lane >> 4) * 8;

    auto load_stage = [&](int s, int k0) {
        uint32_t ab = sA + (uint32_t)(s * GC::ASZ) * 2u;
        uint32_t bb = sB + (uint32_t)(s * GC::BSZ) * 2u;
        #pragma unroll
        for (int it = 0; it < 4; ++it) {
            int e = tid + it * GC::NT;
            int r = e >> 2, c = (e & 3) * 8;
            cp_async16(ab + (uint32_t)(r * GC::LDA + c) * 2u, A + (size_t)(m0 + r) * K + k0 + c);
        }
        #pragma unroll
        for (int it = 0; it < 4; ++it) {
            int e = tid + it * GC::NT;
            int r = e >> 4, c = (e & 15) * 8;
            cp_async16(bb + (uint32_t)(r * GC::LDB + c) * 2u, W + (size_t)(k0 + r) * N + n0 + c);
        }
        cp_async_commit();
    };

    const int nIter = K / GC::BK;
    load_stage(0, 0);
    load_stage(1, GC::BK);
    load_stage(2, 2 * GC::BK);

    for (int it = 0; it < nIter; ++it) {
        cp_async_wait2();
        __syncthreads();

        int nld = it + GC::STAGES - 1;
        if (nld < nIter) load_stage(nld % GC::STAGES, nld * GC::BK);
        else             cp_async_commit();   // keep committed = it+3 invariant

        const int s = it % GC::STAGES;
        const uint32_t Ab = sA + (uint32_t)(s * GC::ASZ) * 2u;
        const uint32_t Bb = sB + (uint32_t)(s * GC::BSZ) * 2u;

        #pragma unroll
        for (int kk = 0; kk < 2; ++kk) {
            uint32_t af[4][4];
            #pragma unroll
            for (int mt = 0; mt < 4; ++mt)
                ldmx4(af[mt][0], af[mt][1], af[mt][2], af[mt][3],
                      Ab + (uint32_t)((wm + mt * 16 + lrow) * GC::LDA + kk * 16 + lcol) * 2u);
            uint32_t bf[16];
            #pragma unroll
            for (int p = 0; p < 4; ++p)
                ldmx4t(bf[p * 4 + 0], bf[p * 4 + 1], bf[p * 4 + 2], bf[p * 4 + 3],
                       Bb + (uint32_t)((kk * 16 + lrow) * GC::LDB + wn + p * 16 + lcol) * 2u);
            #pragma unroll
            for (int nt = 0; nt < 8; ++nt) {
                uint32_t b0 = bf[(nt >> 1) * 4 + (nt & 1) * 2    ];
                uint32_t b1 = bf[(nt >> 1) * 4 + (nt & 1) * 2 + 1];
                #pragma unroll
                for (int mt = 0; mt < 4; ++mt)
                    mma_f16(acc[mt][nt], af[mt], b0, b1);
            }
        }
    }
}

// ---------------------------------------------------------------------------
// Fused Q/K/V projection: blockIdx.x in [0,24): Q 16 / K 4 / V 4 n-blocks.
// ---------------------------------------------------------------------------
__global__ __launch_bounds__(128, 2)
void proj_qkv(const __half* __restrict__ hq, const __half* __restrict__ hk, const __half* __restrict__ hv,
              const __half* __restrict__ hWq, const __half* __restrict__ hWk, const __half* __restrict__ hWv,
              __half* __restrict__ qh, __half* __restrict__ kh, __half* __restrict__ vh)
{
    extern __shared__ __half smh[];
    const int tid  = threadIdx.x;
    const int lane = tid & 31;
    const int wid  = tid >> 5;
    const int g    = lane >> 2;
    const int tg   = lane & 3;

    const int bx = blockIdx.x;
    const __half *A, *W; __half* C; int N, H, nb;
    if (bx < 16)      { A = hq; W = hWq; C = qh; N = EMB;      H = NH;  nb = bx; }
    else if (bx < 20) { A = hk; W = hWk; C = kh; N = NKV * DH; H = NKV; nb = bx - 16; }
    else              { A = hv; W = hWv; C = vh; N = NKV * DH; H = NKV; nb = bx - 20; }

    const int m0 = blockIdx.y * 128;
    const int n0 = nb * 128;
    const int wm = (wid >> 1) * 64;
    const int wn = (wid & 1) * 64;

    float acc[4][8][4];
    #pragma unroll
    for (int i = 0; i < 4; i++)
        #pragma unroll
        for (int j = 0; j < 8; j++)
            #pragma unroll
            for (int r = 0; r < 4; r++) acc[i][j][r] = 0.0f;

    gemm_mainloop(A, W, N, EMB, m0, n0, tid, wid, lane, acc, smh);

    #pragma unroll
    for (int mt = 0; mt < 4; ++mt) {
        int r0 = m0 + wm + mt * 16 + g;
        #pragma unroll
        for (int nt = 0; nt < 8; ++nt) {
            int c = n0 + wn + nt * 8 + 2 * tg;
            int hh = c >> 7, dd = c & (DH - 1);
            {
                int bb = r0 >> 11, ss = r0 & (Sn - 1);
                __half2 t = __floats2half2_rn(acc[mt][nt][0], acc[mt][nt][1]);
                *reinterpret_cast<__half2*>(C + (((size_t)bb * H + hh) * Sn + ss) * DH + dd) = t;
            }
            {
                int r1 = r0 + 8;
                int bb = r1 >> 11, ss = r1 & (Sn - 1);
                __half2 t = __floats2half2_rn(acc[mt][nt][2], acc[mt][nt][3]);
                *reinterpret_cast<__half2*>(C + (((size_t)bb * H + hh) * Sn + ss) * DH + dd) = t;
            }
        }
    }
}

// ---------------------------------------------------------------------------
// Output projection: fp32 row-major out.
// ---------------------------------------------------------------------------
__global__ __launch_bounds__(128, 2)
void proj_out(const __half* __restrict__ A, const __half* __restrict__ W,
              float* __restrict__ C, int M, int N, int K)
{
    extern __shared__ __half smh[];
    const int tid  = threadIdx.x;
    const int lane = tid & 31;
    const int wid  = tid >> 5;
    const int g    = lane >> 2;
    const int tg   = lane & 3;
    const int m0 = blockIdx.y * 128;
    const int n0 = blockIdx.x * 128;
    const int wm = (wid >> 1) * 64;
    const int wn = (wid & 1) * 64;

    float acc[4][8][4];
    #pragma unroll
    for (int i = 0; i < 4; i++)
        #pragma unroll
        for (int j = 0; j < 8; j++)
            #pragma unroll
            for (int r = 0; r < 4; r++) acc[i][j][r] = 0.0f;

    gemm_mainloop(A, W, N, K, m0, n0, tid, wid, lane, acc, smh);

    #pragma unroll
    for (int mt = 0; mt < 4; ++mt) {
        int r0 = m0 + wm + mt * 16 + g;
        #pragma unroll
        for (int nt = 0; nt < 8; ++nt) {
            int c = n0 + wn + nt * 8 + 2 * tg;
            *reinterpret_cast<float2*>(C + (size_t)r0 * N + c) =
                make_float2(acc[mt][nt][0], acc[mt][nt][1]);
            *reinterpret_cast<float2*>(C + (size_t)(r0 + 8) * N + c) =
                make_float2(acc[mt][nt][2], acc[mt][nt][3]);
        }
    }
}

// ---------------------------------------------------------------------------
// Flash attention v4: 128 q-rows/CTA, 128 threads (4 warps x 32 rows),
// 2 CTAs/SM. Q resident in smem (loaded once); K/V double-buffered cp.async
// (wait0-at-top, distance-1 prefetch). Each warp owns 32 q-rows (2 m-tiles),
// halving cross-warp K/V smem redundancy vs the 8-warp layout.
// Base-2 online softmax; mask only diagonal tiles. Grid: (S/128, NH, B).
// ---------------------------------------------------------------------------
#define LDKH 136                 // halves per smem row (272B)
#define QSZH (128 * LDKH)        // Q tile halves
#define KVSZH (128 * LDKH)       // K(64 rows)+V(64 rows) halves per stage

__global__ __launch_bounds__(128, 2)
void attn4(const __half* __restrict__ qh, const __half* __restrict__ kh,
           const __half* __restrict__ vh, __half* __restrict__ z)
{
    extern __shared__ __half smh[];   // Q tile + 2 KV stages
    const int tid  = threadIdx.x;
    const int lane = tid & 31;
    const int wid  = tid >> 5;        // 0..3
    const int g    = lane >> 2;
    const int tg   = lane & 3;
    const int lrow = lane & 15;
    const int lcol = (lane >> 4) * 8;
    const int wm   = wid * 32;        // warp's first q-row in tile

    const int qblk = (int)gridDim.x - 1 - (int)blockIdx.x;  // heavy blocks first
    const int h    = blockIdx.y;
    const int b    = blockIdx.z;
    const int hk   = h >> 2;
    const int q0   = qblk * 128;

    const __half* Qg = qh + (((size_t)b * NH  + h ) * Sn + q0) * DH;
    const __half* Kg = kh + ((size_t)b * NKV + hk) * Sn * DH;
    const __half* Vg = vh + ((size_t)b * NKV + hk) * Sn * DH;

    const uint32_t smbase = (uint32_t)__cvta_generic_to_shared(smh);
    const uint32_t Qb = smbase;

    auto load_kv_async = [&](int bsel, int kt) {
        uint32_t base = smbase + (uint32_t)(QSZH + bsel * KVSZH) * 2u;
        const __half* Kt = Kg + (size_t)kt * 64 * DH;
        const __half* Vt = Vg + (size_t)kt * 64 * DH;
        #pragma unroll
        for (int it = 0; it < 8; ++it) {          // 1024 chunks / 128 threads
            int e = tid + it * 128;
            int r = e >> 4, c = (e & 15) * 8;
            cp_async16(base + (uint32_t)(r * LDKH + c) * 2u,        Kt + (size_t)r * DH + c);
            cp_async16(base + (uint32_t)((64 + r) * LDKH + c) * 2u, Vt + (size_t)r * DH + c);
        }
        cp_async_commit();
    };

    // Q tile -> smem (one group), then prime KV0
    #pragma unroll
    for (int it = 0; it < 16; ++it) {             // 2048 chunks / 128 threads
        int e = tid + it * 128;
        int r = e >> 4, c = (e & 15) * 8;
        cp_async16(Qb + (uint32_t)(r * LDKH + c) * 2u, Qg + (size_t)r * DH + c);
    }
    cp_async_commit();
    load_kv_async(0, 0);

    float O[2][16][4];
    #pragma unroll
    for (int mt = 0; mt < 2; ++mt)
        #pragma unroll
        for (int nv = 0; nv < 16; ++nv)
            #pragma unroll
            for (int i = 0; i < 4; ++i) O[mt][nv][i] = 0.0f;
    float mrow[2][2], lrow2[2][2];
    #pragma unroll
    for (int mt = 0; mt < 2; ++mt) {
        mrow[2 > mt ? mt : 0][0] = -1e30f; mrow[mt][1] = -1e30f;
        lrow2[mt][0] = 0.0f; lrow2[mt][1] = 0.0f;
    }

    const int ktmax = 2 * qblk + 1;

    for (int kt = 0; kt <= ktmax; ++kt) {
        cp_async_wait0();          // Q + all KV <= kt retired
        __syncthreads();

        if (kt + 1 <= ktmax) load_kv_async((kt + 1) & 1, kt + 1);

        const uint32_t Ksb = smbase + (uint32_t)(QSZH + (kt & 1) * KVSZH) * 2u;
        const uint32_t Vsb = Ksb + (uint32_t)(64 * LDKH) * 2u;

        // ---- S = Q K^T for both m-tiles (K fragments shared) ----
        float S[2][8][4];
        #pragma unroll
        for (int mt = 0; mt < 2; ++mt)
            #pragma unroll
            for (int n = 0; n < 8; ++n)
                #pragma unroll
                for (int i = 0; i < 4; ++i) S[mt][n][i] = 0.0f;

        #pragma unroll
        for (int kd = 0; kd < 8; ++kd) {
            uint32_t qf[2][4];
            #pragma unroll
            for (int mt = 0; mt < 2; ++mt)
                ldmx4(qf[mt][0], qf[mt][1], qf[mt][2], qf[mt][3],
                      Qb + (uint32_t)((wm + mt * 16 + lrow) * LDKH + kd * 16 + lcol) * 2u);
            uint32_t bf[16];
            #pragma unroll
            for (int p = 0; p < 4; ++p)
                ldmx4(bf[p * 4 + 0], bf[p * 4 + 1], bf[p * 4 + 2], bf[p * 4 + 3],
                      Ksb + (uint32_t)((p * 16 + lrow) * LDKH + kd * 16 + lcol) * 2u);
            #pragma unroll
            for (int n = 0; n < 8; ++n) {
                uint32_t b0 = bf[(n >> 1) * 4 + (n & 1)    ];
                uint32_t b1 = bf[(n >> 1) * 4 + (n & 1) + 2];
                #pragma unroll
                for (int mt = 0; mt < 2; ++mt)
                    mma_f16(S[mt][n], qf[mt], b0, b1);
            }
        }

        // ---- online softmax (base 2) per m-tile; mask only diagonal tiles ----
        #pragma unroll
        for (int mt = 0; mt < 2; ++mt) {
            float mx0 = -1e30f, mx1 = -1e30f;
            if (kt >= 2 * qblk) {
                const int grow0 = q0 + wm + mt * 16 + g;
                const int grow1 = grow0 + 8;
                const int kb = kt * 64;
                #pragma unroll
                for (int n = 0; n < 8; ++n) {
                    int c = kb + n * 8 + 2 * tg;
                    if (c     > grow0) S[mt][n][0] = -1e30f;
                    if (c + 1 > grow0) S[mt][n][1] = -1e30f;
                    if (c     > grow1) S[mt][n][2] = -1e30f;
                    if (c + 1 > grow1) S[mt][n][3] = -1e30f;
                    mx0 = fmaxf(mx0, fmaxf(S[mt][n][0], S[mt][n][1]));
                    mx1 = fmaxf(mx1, fmaxf(S[mt][n][2], S[mt][n][3]));
                }
            } else {
                #pragma unroll
                for (int n = 0; n < 8; ++n) {
                    mx0 = fmaxf(mx0, fmaxf(S[mt][n][0], S[mt][n][1]));
                    mx1 = fmaxf(mx1, fmaxf(S[mt][n][2], S[mt][n][3]));
                }
            }
            mx0 = fmaxf(mx0, __shfl_xor_sync(0xffffffffu, mx0, 1));
            mx0 = fmaxf(mx0, __shfl_xor_sync(0xffffffffu, mx0, 2));
            mx1 = fmaxf(mx1, __shfl_xor_sync(0xffffffffu, mx1, 1));
            mx1 = fmaxf(mx1, __shfl_xor_sync(0xffffffffu, mx1, 2));

            float mn0 = fmaxf(mrow[mt][0], mx0), mn1 = fmaxf(mrow[mt][1], mx1);
            float al0 = ex2f(mrow[mt][0] - mn0), al1 = ex2f(mrow[mt][1] - mn1);
            mrow[mt][0] = mn0; mrow[mt][1] = mn1;

            float s0 = 0.0f, s1 = 0.0f;
            #pragma unroll
            for (int n = 0; n < 8; ++n) {
                S[mt][n][0] = ex2f(S[mt][n][0] - mn0); s0 += S[mt][n][0];
                S[mt][n][1] = ex2f(S[mt][n][1] - mn0); s0 += S[mt][n][1];
                S[mt][n][2] = ex2f(S[mt][n][2] - mn1); s1 += S[mt][n][2];
                S[mt][n][3] = ex2f(S[mt][n][3] - mn1); s1 += S[mt][n][3];
            }
            s0 += __shfl_xor_sync(0xffffffffu, s0, 1);
            s0 += __shfl_xor_sync(0xffffffffu, s0, 2);
            s1 += __shfl_xor_sync(0xffffffffu, s1, 1);
            s1 += __shfl_xor_sync(0xffffffffu, s1, 2);
            lrow2[mt][0] = lrow2[mt][0] * al0 + s0;
            lrow2[mt][1] = lrow2[mt][1] * al1 + s1;

            #pragma unroll
            for (int nv = 0; nv < 16; ++nv) {
                O[mt][nv][0] *= al0; O[mt][nv][1] *= al0;
                O[mt][nv][2] *= al1; O[mt][nv][3] *= al1;
            }
        }

        // ---- O += P V (V fragments shared across m-tiles) ----
        #pragma unroll
        for (int ks = 0; ks < 4; ++ks) {
            uint32_t a[2][4];
            #pragma unroll
            for (int mt = 0; mt < 2; ++mt) {
                a[mt][0] = packh2(S[mt][2 * ks    ][0], S[mt][2 * ks    ][1]);
                a[mt][1] = packh2(S[mt][2 * ks    ][2], S[mt][2 * ks    ][3]);
                a[mt][2] = packh2(S[mt][2 * ks + 1][0], S[mt][2 * ks + 1][1]);
                a[mt][3] = packh2(S[mt][2 * ks + 1][2], S[mt][2 * ks + 1][3]);
            }
            #pragma unroll
            for (int p = 0; p < 8; ++p) {
                uint32_t r0, r1, r2, r3;
                ldmx4t(r0, r1, r2, r3,
                       Vsb + (uint32_t)((ks * 16 + lrow) * LDKH + p * 16 + lcol) * 2u);
                #pragma unroll
                for (int mt = 0; mt < 2; ++mt) {
                    mma_f16(O[mt][2 * p    ], a[mt], r0, r1);
                    mma_f16(O[mt][2 * p + 1], a[mt], r2, r3);
                }
            }
        }
    }

    // ---- normalize and write Z (fp16) ----
    #pragma unroll
    for (int mt = 0; mt < 2; ++mt) {
        float inv0 = 1.0f / lrow2[mt][0];
        float inv1 = 1.0f / lrow2[mt][1];
        __half* zp = z + ((size_t)b * Sn + q0 + wm + mt * 16) * (NH * DH) + h * DH;
        #pragma unroll
        for (int nv = 0; nv < 16; ++nv) {
            int c = nv * 8 + 2 * tg;
            __half2 v0 = __floats2half2_rn(O[mt][nv][0] * inv0, O[mt][nv][1] * inv0);
            __half2 v1 = __floats2half2_rn(O[mt][nv][2] * inv1, O[mt][nv][3] * inv1);
            *reinterpret_cast<__half2*>(zp + (size_t)(g    ) * (NH * DH) + c) = v0;
            *reinterpret_cast<__half2*>(zp + (size_t)(g + 8) * (NH * DH) + c) = v1;
        }
    }
}

// ---------------------------------------------------------------------------
extern "C" void kernel_launch(void* const* d_in, const int* in_sizes, int n_in,
                              void* d_out, int out_size)
{
    const float* q  = (const float*)d_in[0];
    const float* k  = (const float*)d_in[1];
    const float* v  = (const float*)d_in[2];
    const float* Wq = (const float*)d_in[3];
    const float* Wk = (const float*)d_in[4];
    const float* Wv = (const float*)d_in[5];
    const float* Wo = (const float*)d_in[6];
    float* out = (float*)d_out;

    __half *hq, *hk, *hv, *hWq, *hWk, *hWv, *hWo, *qh, *khp, *vhp, *zbuf;
    cudaGetSymbolAddress((void**)&hq,  g_hq);
    cudaGetSymbolAddress((void**)&hk,  g_hk);
    cudaGetSymbolAddress((void**)&hv,  g_hv);
    cudaGetSymbolAddress((void**)&hWq, g_hWq);
    cudaGetSymbolAddress((void**)&hWk, g_hWk);
    cudaGetSymbolAddress((void**)&hWv, g_hWv);
    cudaGetSymbolAddress((void**)&hWo, g_hWo);
    cudaGetSymbolAddress((void**)&qh,  g_qh);
    cudaGetSymbolAddress((void**)&khp, g_kh);
    cudaGetSymbolAddress((void**)&vhp, g_vh);
    cudaGetSymbolAddress((void**)&zbuf, g_z);

    const float scaleK = 0.29730177875068026f;                 // 128^-0.25
    const float scaleQ = (float)(0.29730177875068026 * 1.4426950408889634);  // * log2(e)

    {
        long total = CVT_TOTAL;
        int blocks = (int)((total + 255) / 256);
        cvt_all<<<blocks, 256>>>(
            (const float4*)q, (const float4*)k, (const float4*)v,
            (const float4*)Wq, (const float4*)Wk, (const float4*)Wv, (const float4*)Wo,
            (uint2*)hq, (uint2*)hk, (uint2*)hv, (uint2*)hWq, (uint2*)hWk, (uint2*)hWv, (uint2*)hWo,
            scaleQ, scaleK);
    }

    const int smemGemm = GemmCore::STAGES * (GemmCore::ASZ + GemmCore::BSZ) * (int)sizeof(__half); // 75776
    cudaFuncSetAttribute(proj_qkv, cudaFuncAttributeMaxDynamicSharedMemorySize, smemGemm);
    cudaFuncSetAttribute(proj_out, cudaFuncAttributeMaxDynamicSharedMemorySize, smemGemm);
    const int smemAttn = (QSZH + 2 * KVSZH) * (int)sizeof(__half);  // 104448
    cudaFuncSetAttribute(attn4, cudaFuncAttributeMaxDynamicSharedMemorySize, smemAttn);

    proj_qkv<<<dim3(24, MROWS / 128), 128, smemGemm>>>(hq, hk, hv, hWq, hWk, hWv, qh, khp, vhp);

    attn4<<<dim3(Sn / 128, NH, Bn), 128, smemAttn>>>(qh, khp, vhp, zbuf);

    proj_out<<<dim3(EMB / 128, MROWS / 128), 128, smemGemm>>>(zbuf, hWo, out, MROWS, EMB, EMB);
}

// round 17
// speedup vs baseline: 1.0200x; 1.0200x over previous
#include <cuda_runtime.h>
#include <cuda_fp16.h>
#include <cstdint>

// Problem constants
#define Bn   2
#define Sn   2048
#define EMB  2048
#define NH   16
#define NKV  4
#define DH   128
#define MROWS (Bn*Sn)   // 4096

// fp16 scratch (device globals; no runtime allocation allowed)
__device__ __half g_hq [(size_t)MROWS*EMB];
__device__ __half g_hk [(size_t)MROWS*EMB];
__device__ __half g_hv [(size_t)MROWS*EMB];
__device__ __half g_hWq[(size_t)EMB*EMB];        // scale*log2e folded
__device__ __half g_hWk[(size_t)EMB*NKV*DH];     // scale folded
__device__ __half g_hWv[(size_t)EMB*NKV*DH];
__device__ __half g_hWo[(size_t)EMB*EMB];
__device__ __half g_qh [(size_t)Bn*NH*Sn*DH];    // [B,H,S,D]
__device__ __half g_kh [(size_t)Bn*NKV*Sn*DH];
__device__ __half g_vh [(size_t)Bn*NKV*Sn*DH];
__device__ __half g_z  [(size_t)Bn*Sn*NH*DH];    // [B,S,H*D]

__device__ __forceinline__ void mma_f16(float c[4], const uint32_t a[4], uint32_t b0, uint32_t b1) {
    asm volatile("mma.sync.aligned.m16n8k16.row.col.f32.f16.f16.f32 "
        "{%0,%1,%2,%3},{%4,%5,%6,%7},{%8,%9},{%0,%1,%2,%3};"
        : "+f"(c[0]), "+f"(c[1]), "+f"(c[2]), "+f"(c[3])
        : "r"(a[0]), "r"(a[1]), "r"(a[2]), "r"(a[3]), "r"(b0), "r"(b1));
}
__device__ __forceinline__ void ldmx4(uint32_t& r0, uint32_t& r1, uint32_t& r2, uint32_t& r3, uint32_t addr) {
    asm volatile("ldmatrix.sync.aligned.m8n8.x4.shared.b16 {%0,%1,%2,%3}, [%4];"
        : "=r"(r0), "=r"(r1), "=r"(r2), "=r"(r3) : "r"(addr));
}
__device__ __forceinline__ void ldmx4t(uint32_t& r0, uint32_t& r1, uint32_t& r2, uint32_t& r3, uint32_t addr) {
    asm volatile("ldmatrix.sync.aligned.m8n8.x4.trans.shared.b16 {%0,%1,%2,%3}, [%4];"
        : "=r"(r0), "=r"(r1), "=r"(r2), "=r"(r3) : "r"(addr));
}
__device__ __forceinline__ uint32_t packh2(float lo, float hi) {
    uint32_t r;
    asm("cvt.rn.f16x2.f32 %0, %1, %2;" : "=r"(r) : "f"(hi), "f"(lo));
    return r;
}
__device__ __forceinline__ float ex2f(float x) {
    float r; asm("ex2.approx.ftz.f32 %0, %1;" : "=f"(r) : "f"(x)); return r;
}
__device__ __forceinline__ void cp_async16(uint32_t saddr, const void* gptr) {
    asm volatile("cp.async.ca.shared.global [%0], [%1], 16;\n"
        :: "r"(saddr), "l"(__cvta_generic_to_global(gptr)));
}
__device__ __forceinline__ void cp_async_commit() { asm volatile("cp.async.commit_group;\n"); }
__device__ __forceinline__ void cp_async_wait1()  { asm volatile("cp.async.wait_group 1;\n"); }
__device__ __forceinline__ void cp_async_wait2()  { asm volatile("cp.async.wait_group 2;\n"); }

// ---------------------------------------------------------------------------
// Fused fp32 -> fp16 convert for all 7 tensors, one launch (simple 1:1 map).
// ---------------------------------------------------------------------------
#define NQ4  ((long)MROWS*EMB/4)
#define WQ4  ((long)EMB*EMB/4)
#define WK4  ((long)EMB*NKV*DH/4)
#define CVT_TOTAL (3*NQ4 + 2*WQ4 + 2*WK4)

__global__ __launch_bounds__(256)
void cvt_all(const float4* __restrict__ q, const float4* __restrict__ k, const float4* __restrict__ v,
             const float4* __restrict__ Wq, const float4* __restrict__ Wk,
             const float4* __restrict__ Wv, const float4* __restrict__ Wo,
             uint2* hq, uint2* hk, uint2* hv, uint2* hWq, uint2* hWk, uint2* hWv, uint2* hWo,
             float scaleQ, float scaleK)
{
    long i = (long)blockIdx.x * blockDim.x + threadIdx.x;
    if (i >= CVT_TOTAL) return;
    const float4* src; uint2* dst; long off; float s = 1.0f;
    if      (i <     NQ4)             { src = q;  dst = hq;  off = i; }
    else if (i < 2 * NQ4)             { src = k;  dst = hk;  off = i - NQ4; }
    else if (i < 3 * NQ4)             { src = v;  dst = hv;  off = i - 2 * NQ4; }
    else if (i < 3 * NQ4 + WQ4)       { src = Wq; dst = hWq; off = i - 3 * NQ4; s = scaleQ; }
    else if (i < 3 * NQ4 + WQ4 + WK4) { src = Wk; dst = hWk; off = i - 3 * NQ4 - WQ4; s = scaleK; }
    else if (i < 3 * NQ4 + WQ4 + 2 * WK4) { src = Wv; dst = hWv; off = i - 3 * NQ4 - WQ4 - WK4; }
    else                              { src = Wo; dst = hWo; off = i - 3 * NQ4 - WQ4 - 2 * WK4; }
    float4 x = src[off];
    __half2 h0 = __floats2half2_rn(x.x * s, x.y * s);
    __half2 h1 = __floats2half2_rn(x.z * s, x.w * s);
    uint2 u; u.x = *reinterpret_cast<uint32_t*>(&h0); u.y = *reinterpret_cast<uint32_t*>(&h1);
    dst[off] = u;
}

// ---------------------------------------------------------------------------
// GEMM core: 128 threads (4 warps, 2x2), warp tile 64x64.
// BM=BN=128, BK=32, 4-stage cp.async; empty-commit tail keeps wait_group 2 sound.
// ---------------------------------------------------------------------------
struct GemmCore {
    static constexpr int BM = 128, BN = 128, BK = 32, STAGES = 4, NT = 128;
    static constexpr int LDA = 40, LDB = 136;
    static constexpr int ASZ = BM * LDA, BSZ = BK * LDB;
};

__device__ __forceinline__ void gemm_mainloop(
    const __half* __restrict__ A, const __half* __restrict__ W,
    int N, int K, int m0, int n0,
    int tid, int wid, int lane, float acc[4][8][4], __half* smh)
{
    using GC = GemmCore;
    const uint32_t sA = (uint32_t)__cvta_generic_to_shared(smh);
    const uint32_t sB = sA + (uint32_t)(GC::STAGES * GC::ASZ) * 2u;
    const int wm = (wid >> 1) * 64;
    const int wn = (wid & 1) * 64;
    const int lrow = lane & 15;
    const int lcol = (lane >> 4) * 8;

    auto load_stage = [&](int s, int k0) {
        uint32_t ab = sA + (uint32_t)(s * GC::ASZ) * 2u;
        uint32_t bb = sB + (uint32_t)(s * GC::BSZ) * 2u;
        #pragma unroll
        for (int it = 0; it < 4; ++it) {
            int e = tid + it * GC::NT;
            int r = e >> 2, c = (e & 3) * 8;
            cp_async16(ab + (uint32_t)(r * GC::LDA + c) * 2u, A + (size_t)(m0 + r) * K + k0 + c);
        }
        #pragma unroll
        for (int it = 0; it < 4; ++it) {
            int e = tid + it * GC::NT;
            int r = e >> 4, c = (e & 15) * 8;
            cp_async16(bb + (uint32_t)(r * GC::LDB + c) * 2u, W + (size_t)(k0 + r) * N + n0 + c);
        }
        cp_async_commit();
    };

    const int nIter = K / GC::BK;
    load_stage(0, 0);
    load_stage(1, GC::BK);
    load_stage(2, 2 * GC::BK);

    for (int it = 0; it < nIter; ++it) {
        cp_async_wait2();
        __syncthreads();

        int nld = it + GC::STAGES - 1;
        if (nld < nIter) load_stage(nld % GC::STAGES, nld * GC::BK);
        else             cp_async_commit();   // keep committed = it+3 invariant

        const int s = it % GC::STAGES;
        const uint32_t Ab = sA + (uint32_t)(s * GC::ASZ) * 2u;
        const uint32_t Bb = sB + (uint32_t)(s * GC::BSZ) * 2u;

        #pragma unroll
        for (int kk = 0; kk < 2; ++kk) {
            uint32_t af[4][4];
            #pragma unroll
            for (int mt = 0; mt < 4; ++mt)
                ldmx4(af[mt][0], af[mt][1], af[mt][2], af[mt][3],
                      Ab + (uint32_t)((wm + mt * 16 + lrow) * GC::LDA + kk * 16 + lcol) * 2u);
            uint32_t bf[16];
            #pragma unroll
            for (int p = 0; p < 4; ++p)
                ldmx4t(bf[p * 4 + 0], bf[p * 4 + 1], bf[p * 4 + 2], bf[p * 4 + 3],
                       Bb + (uint32_t)((kk * 16 + lrow) * GC::LDB + wn + p * 16 + lcol) * 2u);
            #pragma unroll
            for (int nt = 0; nt < 8; ++nt) {
                uint32_t b0 = bf[(nt >> 1) * 4 + (nt & 1) * 2    ];
                uint32_t b1 = bf[(nt >> 1) * 4 + (nt & 1) * 2 + 1];
                #pragma unroll
                for (int mt = 0; mt < 4; ++mt)
                    mma_f16(acc[mt][nt], af[mt], b0, b1);
            }
        }
    }
}

// ---------------------------------------------------------------------------
// Fused Q/K/V projection: blockIdx.x in [0,24): Q 16 / K 4 / V 4 n-blocks.
// ---------------------------------------------------------------------------
__global__ __launch_bounds__(128, 2)
void proj_qkv(const __half* __restrict__ hq, const __half* __restrict__ hk, const __half* __restrict__ hv,
              const __half* __restrict__ hWq, const __half* __restrict__ hWk, const __half* __restrict__ hWv,
              __half* __restrict__ qh, __half* __restrict__ kh, __half* __restrict__ vh)
{
    extern __shared__ __half smh[];
    const int tid  = threadIdx.x;
    const int lane = tid & 31;
    const int wid  = tid >> 5;
    const int g    = lane >> 2;
    const int tg   = lane & 3;

    const int bx = blockIdx.x;
    const __half *A, *W; __half* C; int N, H, nb;
    if (bx < 16)      { A = hq; W = hWq; C = qh; N = EMB;      H = NH;  nb = bx; }
    else if (bx < 20) { A = hk; W = hWk; C = kh; N = NKV * DH; H = NKV; nb = bx - 16; }
    else              { A = hv; W = hWv; C = vh; N = NKV * DH; H = NKV; nb = bx - 20; }

    const int m0 = blockIdx.y * 128;
    const int n0 = nb * 128;
    const int wm = (wid >> 1) * 64;
    const int wn = (wid & 1) * 64;

    float acc[4][8][4];
    #pragma unroll
    for (int i = 0; i < 4; i++)
        #pragma unroll
        for (int j = 0; j < 8; j++)
            #pragma unroll
            for (int r = 0; r < 4; r++) acc[i][j][r] = 0.0f;

    gemm_mainloop(A, W, N, EMB, m0, n0, tid, wid, lane, acc, smh);

    #pragma unroll
    for (int mt = 0; mt < 4; ++mt) {
        int r0 = m0 + wm + mt * 16 + g;
        #pragma unroll
        for (int nt = 0; nt < 8; ++nt) {
            int c = n0 + wn + nt * 8 + 2 * tg;
            int hh = c >> 7, dd = c & (DH - 1);
            {
                int bb = r0 >> 11, ss = r0 & (Sn - 1);
                __half2 t = __floats2half2_rn(acc[mt][nt][0], acc[mt][nt][1]);
                *reinterpret_cast<__half2*>(C + (((size_t)bb * H + hh) * Sn + ss) * DH + dd) = t;
            }
            {
                int r1 = r0 + 8;
                int bb = r1 >> 11, ss = r1 & (Sn - 1);
                __half2 t = __floats2half2_rn(acc[mt][nt][2], acc[mt][nt][3]);
                *reinterpret_cast<__half2*>(C + (((size_t)bb * H + hh) * Sn + ss) * DH + dd) = t;
            }
        }
    }
}

// ---------------------------------------------------------------------------
// Output projection: fp32 row-major out.
// ---------------------------------------------------------------------------
__global__ __launch_bounds__(128, 2)
void proj_out(const __half* __restrict__ A, const __half* __restrict__ W,
              float* __restrict__ C, int M, int N, int K)
{
    extern __shared__ __half smh[];
    const int tid  = threadIdx.x;
    const int lane = tid & 31;
    const int wid  = tid >> 5;
    const int g    = lane >> 2;
    const int tg   = lane & 3;
    const int m0 = blockIdx.y * 128;
    const int n0 = blockIdx.x * 128;
    const int wm = (wid >> 1) * 64;
    const int wn = (wid & 1) * 64;

    float acc[4][8][4];
    #pragma unroll
    for (int i = 0; i < 4; i++)
        #pragma unroll
        for (int j = 0; j < 8; j++)
            #pragma unroll
            for (int r = 0; r < 4; r++) acc[i][j][r] = 0.0f;

    gemm_mainloop(A, W, N, K, m0, n0, tid, wid, lane, acc, smh);

    #pragma unroll
    for (int mt = 0; mt < 4; ++mt) {
        int r0 = m0 + wm + mt * 16 + g;
        #pragma unroll
        for (int nt = 0; nt < 8; ++nt) {
            int c = n0 + wn + nt * 8 + 2 * tg;
            *reinterpret_cast<float2*>(C + (size_t)r0 * N + c) =
                make_float2(acc[mt][nt][0], acc[mt][nt][1]);
            *reinterpret_cast<float2*>(C + (size_t)(r0 + 8) * N + c) =
                make_float2(acc[mt][nt][2], acc[mt][nt][3]);
        }
    }
}

// ---------------------------------------------------------------------------
// Flash attention (best measured config): 128 q-rows/CTA, 256 threads,
// 64-key tiles, 3-stage K/V cp.async. Base-2 online softmax; mask only
// diagonal tiles. Grid: (S/128, NH, B).
// ---------------------------------------------------------------------------
#define LDKH 136   // halves per K/V smem row (272B)

__global__ __launch_bounds__(256, 1)
void attn3(const __half* __restrict__ qh, const __half* __restrict__ kh,
           const __half* __restrict__ vh, __half* __restrict__ z)
{
    extern __shared__ __half smh[];   // 3 bufs x (K 64x136 + V 64x136)
    const int tid  = threadIdx.x;
    const int lane = tid & 31;
    const int w    = tid >> 5;
    const int g    = lane >> 2;
    const int tg   = lane & 3;
    const int lrow = lane & 15;
    const int lcol = (lane >> 4) * 8;

    const int qblk = (int)gridDim.x - 1 - (int)blockIdx.x;  // heavy blocks first
    const int h    = blockIdx.y;
    const int b    = blockIdx.z;
    const int hk   = h >> 2;
    const int q0   = qblk * 128;

    const __half* Qg = qh + (((size_t)b * NH  + h ) * Sn + q0) * DH;
    const __half* Kg = kh + ((size_t)b * NKV + hk) * Sn * DH;
    const __half* Vg = vh + ((size_t)b * NKV + hk) * Sn * DH;

    const uint32_t smbase = (uint32_t)__cvta_generic_to_shared(smh);
    constexpr int BUFF = 2 * 64 * LDKH;

    auto load_kv_async = [&](int bsel, int kt) {
        uint32_t base = smbase + (uint32_t)(bsel * BUFF) * 2u;
        const __half* Kt = Kg + (size_t)kt * 64 * DH;
        const __half* Vt = Vg + (size_t)kt * 64 * DH;
        #pragma unroll
        for (int it = 0; it < 4; ++it) {
            int e = tid + it * 256;
            int r = e >> 4, c = (e & 15) * 8;
            cp_async16(base + (uint32_t)(r * LDKH + c) * 2u,        Kt + (size_t)r * DH + c);
            cp_async16(base + (uint32_t)((64 + r) * LDKH + c) * 2u, Vt + (size_t)r * DH + c);
        }
        cp_async_commit();
    };

    const int ktmax = 2 * qblk + 1;

    load_kv_async(0, 0);
    load_kv_async(1, 1);

    uint32_t Qa[8][4];
    {
        const __half* qw = Qg + (size_t)(w * 16) * DH;
        #pragma unroll
        for (int ks = 0; ks < 8; ++ks) {
            Qa[ks][0] = *reinterpret_cast<const uint32_t*>(qw + (size_t)(g    ) * DH + ks * 16 + 2 * tg);
            Qa[ks][1] = *reinterpret_cast<const uint32_t*>(qw + (size_t)(g + 8) * DH + ks * 16 + 2 * tg);
            Qa[ks][2] = *reinterpret_cast<const uint32_t*>(qw + (size_t)(g    ) * DH + ks * 16 + 8 + 2 * tg);
            Qa[ks][3] = *reinterpret_cast<const uint32_t*>(qw + (size_t)(g + 8) * DH + ks * 16 + 8 + 2 * tg);
        }
    }

    float O[16][4];
    #pragma unroll
    for (int nv = 0; nv < 16; ++nv)
        #pragma unroll
        for (int i = 0; i < 4; ++i) O[nv][i] = 0.0f;
    float m0 = -1e30f, m1 = -1e30f, l0 = 0.0f, l1 = 0.0f;

    for (int kt = 0; kt <= ktmax; ++kt) {
        cp_async_wait1();
        __syncthreads();

        int nk = kt + 2;
        if (nk <= ktmax) load_kv_async(nk % 3, nk);
        else             cp_async_commit();

        const uint32_t Ksb = smbase + (uint32_t)((kt % 3) * BUFF) * 2u;
        const uint32_t Vsb = Ksb + (uint32_t)(64 * LDKH) * 2u;

        // ---- S = Q K^T (base-2 logits) ----
        float S[8][4];
        #pragma unroll
        for (int n = 0; n < 8; ++n)
            #pragma unroll
            for (int i = 0; i < 4; ++i) S[n][i] = 0.0f;

        #pragma unroll
        for (int kd = 0; kd < 8; ++kd) {
            uint32_t bf[16];
            #pragma unroll
            for (int p = 0; p < 4; ++p)
                ldmx4(bf[p * 4 + 0], bf[p * 4 + 1], bf[p * 4 + 2], bf[p * 4 + 3],
                      Ksb + (uint32_t)((p * 16 + lrow) * LDKH + kd * 16 + lcol) * 2u);
            #pragma unroll
            for (int n = 0; n < 8; ++n) {
                uint32_t b0 = bf[(n >> 1) * 4 + (n & 1)    ];
                uint32_t b1 = bf[(n >> 1) * 4 + (n & 1) + 2];
                mma_f16(S[n], Qa[kd], b0, b1);
            }
        }

        // ---- online softmax (base 2); mask only on diagonal tiles ----
        float mx0 = -1e30f, mx1 = -1e30f;
        if (kt >= 2 * qblk) {
            const int grow0 = q0 + w * 16 + g;
            const int grow1 = grow0 + 8;
            const int kb = kt * 64;
            #pragma unroll
            for (int n = 0; n < 8; ++n) {
                int c = kb + n * 8 + 2 * tg;
                if (c     > grow0) S[n][0] = -1e30f;
                if (c + 1 > grow0) S[n][1] = -1e30f;
                if (c     > grow1) S[n][2] = -1e30f;
                if (c + 1 > grow1) S[n][3] = -1e30f;
                mx0 = fmaxf(mx0, fmaxf(S[n][0], S[n][1]));
                mx1 = fmaxf(mx1, fmaxf(S[n][2], S[n][3]));
            }
        } else {
            #pragma unroll
            for (int n = 0; n < 8; ++n) {
                mx0 = fmaxf(mx0, fmaxf(S[n][0], S[n][1]));
                mx1 = fmaxf(mx1, fmaxf(S[n][2], S[n][3]));
            }
        }
        mx0 = fmaxf(mx0, __shfl_xor_sync(0xffffffffu, mx0, 1));
        mx0 = fmaxf(mx0, __shfl_xor_sync(0xffffffffu, mx0, 2));
        mx1 = fmaxf(mx1, __shfl_xor_sync(0xffffffffu, mx1, 1));
        mx1 = fmaxf(mx1, __shfl_xor_sync(0xffffffffu, mx1, 2));

        float mn0 = fmaxf(m0, mx0), mn1 = fmaxf(m1, mx1);
        float al0 = ex2f(m0 - mn0), al1 = ex2f(m1 - mn1);
        m0 = mn0; m1 = mn1;

        float s0 = 0.0f, s1 = 0.0f;
        #pragma unroll
        for (int n = 0; n < 8; ++n) {
            S[n][0] = ex2f(S[n][0] - mn0); s0 += S[n][0];
            S[n][1] = ex2f(S[n][1] - mn0); s0 += S[n][1];
            S[n][2] = ex2f(S[n][2] - mn1); s1 += S[n][2];
            S[n][3] = ex2f(S[n][3] - mn1); s1 += S[n][3];
        }
        s0 += __shfl_xor_sync(0xffffffffu, s0, 1);
        s0 += __shfl_xor_sync(0xffffffffu, s0, 2);
        s1 += __shfl_xor_sync(0xffffffffu, s1, 1);
        s1 += __shfl_xor_sync(0xffffffffu, s1, 2);
        l0 = l0 * al0 + s0;
        l1 = l1 * al1 + s1;

        #pragma unroll
        for (int nv = 0; nv < 16; ++nv) {
            O[nv][0] *= al0; O[nv][1] *= al0;
            O[nv][2] *= al1; O[nv][3] *= al1;
        }

        // ---- O += P V ----
        #pragma unroll
        for (int ks = 0; ks < 4; ++ks) {
            uint32_t a[4];
            a[0] = packh2(S[2 * ks    ][0], S[2 * ks    ][1]);
            a[1] = packh2(S[2 * ks    ][2], S[2 * ks    ][3]);
            a[2] = packh2(S[2 * ks + 1][0], S[2 * ks + 1][1]);
            a[3] = packh2(S[2 * ks + 1][2], S[2 * ks + 1][3]);
            #pragma unroll
            for (int p = 0; p < 8; ++p) {
                uint32_t r0, r1, r2, r3;
                ldmx4t(r0, r1, r2, r3,
                       Vsb + (uint32_t)((ks * 16 + lrow) * LDKH + p * 16 + lcol) * 2u);
                mma_f16(O[2 * p    ], a, r0, r1);
                mma_f16(O[2 * p + 1], a, r2, r3);
            }
        }
    }

    // ---- normalize and write Z (fp16) ----
    float inv0 = 1.0f / l0;
    float inv1 = 1.0f / l1;
    __half* zp = z + ((size_t)b * Sn + q0 + w * 16) * (NH * DH) + h * DH;
    #pragma unroll
    for (int nv = 0; nv < 16; ++nv) {
        int c = nv * 8 + 2 * tg;
        __half2 v0 = __floats2half2_rn(O[nv][0] * inv0, O[nv][1] * inv0);
        __half2 v1 = __floats2half2_rn(O[nv][2] * inv1, O[nv][3] * inv1);
        *reinterpret_cast<__half2*>(zp + (size_t)(g    ) * (NH * DH) + c) = v0;
        *reinterpret_cast<__half2*>(zp + (size_t)(g + 8) * (NH * DH) + c) = v1;
    }
}

// ---------------------------------------------------------------------------
extern "C" void kernel_launch(void* const* d_in, const int* in_sizes, int n_in,
                              void* d_out, int out_size)
{
    const float* q  = (const float*)d_in[0];
    const float* k  = (const float*)d_in[1];
    const float* v  = (const float*)d_in[2];
    const float* Wq = (const float*)d_in[3];
    const float* Wk = (const float*)d_in[4];
    const float* Wv = (const float*)d_in[5];
    const float* Wo = (const float*)d_in[6];
    float* out = (float*)d_out;

    __half *hq, *hk, *hv, *hWq, *hWk, *hWv, *hWo, *qh, *khp, *vhp, *zbuf;
    cudaGetSymbolAddress((void**)&hq,  g_hq);
    cudaGetSymbolAddress((void**)&hk,  g_hk);
    cudaGetSymbolAddress((void**)&hv,  g_hv);
    cudaGetSymbolAddress((void**)&hWq, g_hWq);
    cudaGetSymbolAddress((void**)&hWk, g_hWk);
    cudaGetSymbolAddress((void**)&hWv, g_hWv);
    cudaGetSymbolAddress((void**)&hWo, g_hWo);
    cudaGetSymbolAddress((void**)&qh,  g_qh);
    cudaGetSymbolAddress((void**)&khp, g_kh);
    cudaGetSymbolAddress((void**)&vhp, g_vh);
    cudaGetSymbolAddress((void**)&zbuf, g_z);

    const float scaleK = 0.29730177875068026f;                 // 128^-0.25
    const float scaleQ = (float)(0.29730177875068026 * 1.4426950408889634);  // * log2(e)

    {
        long total = CVT_TOTAL;
        int blocks = (int)((total + 255) / 256);
        cvt_all<<<blocks, 256>>>(
            (const float4*)q, (const float4*)k, (const float4*)v,
            (const float4*)Wq, (const float4*)Wk, (const float4*)Wv, (const float4*)Wo,
            (uint2*)hq, (uint2*)hk, (uint2*)hv, (uint2*)hWq, (uint2*)hWk, (uint2*)hWv, (uint2*)hWo,
            scaleQ, scaleK);
    }

    const int smemGemm = GemmCore::STAGES * (GemmCore::ASZ + GemmCore::BSZ) * (int)sizeof(__half); // 75776
    cudaFuncSetAttribute(proj_qkv, cudaFuncAttributeMaxDynamicSharedMemorySize, smemGemm);
    cudaFuncSetAttribute(proj_out, cudaFuncAttributeMaxDynamicSharedMemorySize, smemGemm);
    const int smemAttn = 3 * 2 * 64 * LDKH * (int)sizeof(__half);  // 104448
    cudaFuncSetAttribute(attn3, cudaFuncAttributeMaxDynamicSharedMemorySize, smemAttn);

    proj_qkv<<<dim3(24, MROWS / 128), 128, smemGemm>>>(hq, hk, hv, hWq, hWk, hWv, qh, khp, vhp);

    attn3<<<dim3(Sn / 128, NH, Bn), 256, smemAttn>>>(qh, khp, vhp, zbuf);

    proj_out<<<dim3(EMB / 128, MROWS / 128), 128, smemGemm>>>(zbuf, hWo, out, MROWS, EMB, EMB);
}